// round 13
// baseline (speedup 1.0000x reference)
#include <cuda_runtime.h>
#include <cuda_fp16.h>
#include <cstdint>

static constexpr int BSZ = 16384;
static constexpr int HD  = 1024;
static constexpr int DD  = 512;

// ---------------- device scratch (allocation-free contract) ----------------
__device__ __align__(256) __half g_x_h [(size_t)BSZ * DD];
__device__ __align__(256) __half g_h0_h[(size_t)BSZ * HD];
__device__ __align__(256) __half g_h1_h[(size_t)BSZ * HD];
__device__ __align__(256) __half g_w0_h[(size_t)4 * HD * DD];
__device__ __align__(256) __half g_w1_h[(size_t)4 * HD * HD];
__device__ __align__(256) __half g_wd_h[(size_t)DD * HD];

// ---------------- helpers ----------------
__device__ __forceinline__ uint32_t smem_u32(const void* p) {
    uint32_t a;
    asm("{ .reg .u64 t; cvta.to.shared.u64 t, %1; cvt.u32.u64 %0, t; }" : "=r"(a) : "l"(p));
    return a;
}
__device__ __forceinline__ void cpa16(uint32_t dst, const void* src) {
    asm volatile("cp.async.cg.shared.global [%0], [%1], 16;\n" :: "r"(dst), "l"(src));
}
__device__ __forceinline__ void ldsm4(uint32_t* r, uint32_t a) {
    asm volatile("ldmatrix.sync.aligned.m8n8.x4.shared.b16 {%0,%1,%2,%3}, [%4];"
        : "=r"(r[0]), "=r"(r[1]), "=r"(r[2]), "=r"(r[3]) : "r"(a));
}
// f32-accumulate mma (decoder path; proven at the 277 TF/s ceiling)
__device__ __forceinline__ void mma16816(float* d, const uint32_t* a, const uint32_t* b) {
    asm volatile("mma.sync.aligned.m16n8k16.row.col.f32.f16.f16.f32 "
        "{%0,%1,%2,%3}, {%4,%5,%6,%7}, {%8,%9}, {%0,%1,%2,%3};"
        : "+f"(d[0]), "+f"(d[1]), "+f"(d[2]), "+f"(d[3])
        : "r"(a[0]), "r"(a[1]), "r"(a[2]), "r"(a[3]), "r"(b[0]), "r"(b[1]));
}
// f16-accumulate mma, fresh zero C (rate probe). D: d0 = {c0,c1} (row l/4),
// d1 = {c2,c3} (row l/4+8) -> same output positions as the f32 variant.
__device__ __forceinline__ void mma16816h(uint32_t* d, const uint32_t* a, const uint32_t* b) {
    asm volatile("mma.sync.aligned.m16n8k16.row.col.f16.f16.f16.f16 "
        "{%0,%1}, {%2,%3,%4,%5}, {%6,%7}, {%8,%8};"
        : "=r"(d[0]), "=r"(d[1])
        : "r"(a[0]), "r"(a[1]), "r"(a[2]), "r"(a[3]),
          "r"(b[0]), "r"(b[1]), "r"(0u));
}
// promote packed half2 into two fp32 accumulators
__device__ __forceinline__ void padd(float* a2, uint32_t h2) {
    asm("{ .reg .f16 l, h; .reg .f32 fl, fh;\n\t"
        "mov.b32 {l, h}, %2;\n\t"
        "cvt.f32.f16 fl, l;\n\t"
        "cvt.f32.f16 fh, h;\n\t"
        "add.f32 %0, %0, fl;\n\t"
        "add.f32 %1, %1, fh; }"
        : "+f"(a2[0]), "+f"(a2[1]) : "r"(h2));
}
__device__ __forceinline__ float sigm(float x) { return 1.0f / (1.0f + __expf(-x)); }
__device__ __forceinline__ float tanh_e(float x) {
    float ax = fabsf(x);
    float e  = __expf(2.0f * ax);
    float t  = 1.0f - 2.0f / (1.0f + e);
    return copysignf(t, x);
}

// ---------------- fp32 -> fp16 conversion ----------------
__global__ void cvt_h_kernel(const float4* __restrict__ src, __half2* __restrict__ dst, int n4) {
    int i = blockIdx.x * blockDim.x + threadIdx.x;
    if (i >= n4) return;
    float4 v = src[i];
    dst[2 * i + 0] = __floats2half2_rn(v.x, v.y);
    dst[2 * i + 1] = __floats2half2_rn(v.z, v.w);
}

// ---------------- fused mma.sync GEMM (fp16, 2-stage, occ=2 CTAs/SM) ----------
// NG==3: gates i/g/o of A @ W^T (f-gate dead), LSTM-cell epilogue -> h (fp16).
// NG==1: decoder A @ W^T + b -> fp32.
// HACC: use f16-accumulate mma (fresh C per k16) + promote to fp32 (rate probe).
template<int K, int NG, int NT, bool HACC>
__global__ void __launch_bounds__(256, 2)
mm_kernel(const __half* __restrict__ Ah, const __half* __restrict__ Wh,
          const float* __restrict__ b0, const float* __restrict__ b1,
          float* __restrict__ outF, __half* __restrict__ outH)
{
    constexpr int PITCH  = 144;              // 64 fp16 + 8 pad -> ldmatrix conflict-free
    constexpr int ASZ    = 128 * PITCH;
    constexpr int WSZ    = NT * PITCH;
    constexpr int STAGE  = ASZ + NG * WSZ;
    constexpr int NSTG   = 2;
    constexpr int NCHUNK = K / 64;
    constexpr int NFRAG  = NT / 16;          // n8 frags per warp per gate (warp spans NT/2)
    constexpr int NPAIR  = NFRAG / 2;

    extern __shared__ char smem[];
    const uint32_t sb = smem_u32(smem);
    float* bs = (float*)(smem + NSTG * STAGE);

    const int tid = threadIdx.x, wid = tid >> 5, lane = tid & 31;
    const int wm = wid & 3, wn = wid >> 2;
    const int row0 = blockIdx.y * 128, col0 = blockIdx.x * NT;

    // bias sums -> smem (consumed only in epilogue; barriers in between)
    for (int i = tid; i < NG * NT; i += 256) {
        int g = i / NT, n = i - g * NT;
        int go = (NG == 3) ? ((g == 0) ? 0 : (g == 1 ? 2 * HD : 3 * HD)) : 0;
        float bv = b0[go + col0 + n];
        if (NG == 3) bv += b1[go + col0 + n];
        bs[i] = bv;
    }

    const int lr = tid >> 3;     // 0..31 row within 32-row slab
    const int lc = tid & 7;      // 16B chunk within 64-fp16 row

    auto load_chunk = [&](int s, int ck) {
        const int k0 = ck * 64;
        const uint32_t st = sb + s * STAGE;
        #pragma unroll
        for (int it = 0; it < 4; it++) {
            int r = lr + it * 32;
            cpa16(st + r * PITCH + lc * 16, Ah + (size_t)(row0 + r) * K + k0 + lc * 8);
        }
        #pragma unroll
        for (int g = 0; g < NG; g++) {
            const int go = (NG == 3) ? ((g == 0) ? 0 : (g == 1 ? 2 * HD : 3 * HD)) : 0;
            uint32_t wb = st + ASZ + g * WSZ;
            #pragma unroll
            for (int it = 0; it < NT / 32; it++) {
                int r = lr + it * 32;
                cpa16(wb + r * PITCH + lc * 16,
                      Wh + (size_t)(go + col0 + r) * K + k0 + lc * 8);
            }
        }
        asm volatile("cp.async.commit_group;" ::: "memory");
    };

    // ldmatrix per-lane base offsets.
    uint32_t aOff[2];
    #pragma unroll
    for (int f = 0; f < 2; f++)
        aOff[f] = (uint32_t)((wm * 32 + f * 16 + (lane & 15)) * PITCH + (lane >> 4) * 16);
    // W stored [n][k] -> non-trans ldmatrix gives exactly the B fragment (n = l/4, k = 2*(l%4)).
    uint32_t bOff[NPAIR];
    #pragma unroll
    for (int p = 0; p < NPAIR; p++)
        bOff[p] = (uint32_t)((wn * (NT / 2) + p * 16 + (lane & 7) + ((lane >> 4) & 1) * 8) * PITCH
                             + ((lane >> 3) & 1) * 16);

    float acc[NG][2][NFRAG][4];
    #pragma unroll
    for (int g = 0; g < NG; g++)
        #pragma unroll
        for (int f = 0; f < 2; f++)
            #pragma unroll
            for (int j = 0; j < NFRAG; j++)
                #pragma unroll
                for (int q = 0; q < 4; q++) acc[g][f][j][q] = 0.0f;

    load_chunk(0, 0);

    // 2-stage mainloop, ONE barrier per chunk.
    for (int k = 0; k < NCHUNK; k++) {
        const int s = k % NSTG;
        asm volatile("cp.async.wait_group 0;" ::: "memory");
        __syncthreads();
        if (k + 1 < NCHUNK) load_chunk((k + 1) % NSTG, k + 1);

        const uint32_t st = sb + s * STAGE;
        #pragma unroll
        for (int ks = 0; ks < 4; ks++) {
            uint32_t aF[2][4];
            ldsm4(aF[0], st + aOff[0] + ks * 32);
            ldsm4(aF[1], st + aOff[1] + ks * 32);
            #pragma unroll
            for (int g = 0; g < NG; g++) {
                const uint32_t wb = st + ASZ + g * WSZ;
                uint32_t bh[NPAIR][4];
                #pragma unroll
                for (int p = 0; p < NPAIR; p++)
                    ldsm4(bh[p], wb + bOff[p] + ks * 32);
                if constexpr (HACC) {
                    uint32_t dh[2][NFRAG][2];
                    #pragma unroll
                    for (int f = 0; f < 2; f++)
                        #pragma unroll
                        for (int j = 0; j < NFRAG; j++)
                            mma16816h(dh[f][j], aF[f], &bh[j >> 1][(j & 1) * 2]);
                    #pragma unroll
                    for (int f = 0; f < 2; f++)
                        #pragma unroll
                        for (int j = 0; j < NFRAG; j++) {
                            padd(&acc[g][f][j][0], dh[f][j][0]);
                            padd(&acc[g][f][j][2], dh[f][j][1]);
                        }
                } else {
                    #pragma unroll
                    for (int f = 0; f < 2; f++)
                        #pragma unroll
                        for (int j = 0; j < NFRAG; j++)
                            mma16816(acc[g][f][j], aF[f], &bh[j >> 1][(j & 1) * 2]);
                }
            }
        }
    }

    // ---------------- epilogue ----------------
    const int mBase = row0 + wm * 32 + (lane >> 2);
    const int nLoc0 = wn * (NT / 2) + (lane & 3) * 2;      // col offset within tile

    if constexpr (NG == 3) {
        #pragma unroll
        for (int f = 0; f < 2; f++)
            #pragma unroll
            for (int j = 0; j < NFRAG; j++)
                #pragma unroll
                for (int hh = 0; hh < 2; hh++) {
                    int m = mBase + f * 16 + hh * 8;
                    int nl = nLoc0 + j * 8;
                    float h2[2];
                    #pragma unroll
                    for (int u = 0; u < 2; u++) {
                        float iv = sigm(acc[0][f][j][hh * 2 + u] + bs[0 * NT + nl + u]);
                        float gv = tanh_e(acc[1][f][j][hh * 2 + u] + bs[1 * NT + nl + u]);
                        float ov = sigm(acc[2][f][j][hh * 2 + u] + bs[2 * NT + nl + u]);
                        h2[u] = ov * tanh_e(iv * gv);
                    }
                    *(__half2*)(outH + (size_t)m * HD + col0 + nl) = __floats2half2_rn(h2[0], h2[1]);
                }
    } else {
        #pragma unroll
        for (int f = 0; f < 2; f++)
            #pragma unroll
            for (int j = 0; j < NFRAG; j++)
                #pragma unroll
                for (int hh = 0; hh < 2; hh++) {
                    int m = mBase + f * 16 + hh * 8;
                    int nl = nLoc0 + j * 8;
                    float2 v;
                    v.x = acc[0][f][j][hh * 2 + 0] + bs[nl + 0];
                    v.y = acc[0][f][j][hh * 2 + 1] + bs[nl + 1];
                    *(float2*)(outF + (size_t)m * DD + col0 + nl) = v;
                }
    }
}

// ---------------- launch ----------------
extern "C" void kernel_launch(void* const* d_in, const int* in_sizes, int n_in,
                              void* d_out, int out_size) {
    const float* x     = (const float*)d_in[0];
    const float* W_ih0 = (const float*)d_in[1];
    const float* b_ih0 = (const float*)d_in[3];
    const float* b_hh0 = (const float*)d_in[4];
    const float* W_ih1 = (const float*)d_in[5];
    const float* b_ih1 = (const float*)d_in[7];
    const float* b_hh1 = (const float*)d_in[8];
    const float* W_dec = (const float*)d_in[9];
    const float* b_dec = (const float*)d_in[10];
    float* out = (float*)d_out;

    __half *xh, *h0h, *h1h, *w0h, *w1h, *wdh;
    cudaGetSymbolAddress((void**)&xh,  g_x_h);
    cudaGetSymbolAddress((void**)&h0h, g_h0_h);
    cudaGetSymbolAddress((void**)&h1h, g_h1_h);
    cudaGetSymbolAddress((void**)&w0h, g_w0_h);
    cudaGetSymbolAddress((void**)&w1h, g_w1_h);
    cudaGetSymbolAddress((void**)&wdh, g_wd_h);

    // shared-memory sizes (2 stages; 2 CTAs/SM: 2 x 92928 = 186 KB < 228 KB)
    constexpr int PITCH = 144;
    constexpr int STAGE_L = 128 * PITCH + 3 * 64 * PITCH;     // 46080
    constexpr int STAGE_D = 128 * PITCH + 1 * 64 * PITCH;     // 27648
    constexpr int SM_L = 2 * STAGE_L + 3 * 64 * 4;            // 92928
    constexpr int SM_D = 2 * STAGE_D + 1 * 64 * 4;            // 55552
    cudaFuncSetAttribute(mm_kernel<DD, 3, 64, true>,  cudaFuncAttributeMaxDynamicSharedMemorySize, SM_L);
    cudaFuncSetAttribute(mm_kernel<HD, 3, 64, true>,  cudaFuncAttributeMaxDynamicSharedMemorySize, SM_L);
    cudaFuncSetAttribute(mm_kernel<HD, 1, 64, false>, cudaFuncAttributeMaxDynamicSharedMemorySize, SM_D);

    // conversions (plain fp16)
    auto cvt = [&](const float* src, __half* dst, size_t n) {
        int n4 = (int)(n / 4);
        cvt_h_kernel<<<(n4 + 255) / 256, 256>>>((const float4*)src, (__half2*)dst, n4);
    };
    cvt(x,     xh,  (size_t)BSZ * DD);
    cvt(W_ih0, w0h, (size_t)4 * HD * DD);
    cvt(W_ih1, w1h, (size_t)4 * HD * HD);
    cvt(W_dec, wdh, (size_t)DD * HD);

    dim3 blk(256);
    dim3 gL(HD / 64, BSZ / 128);    // 16 x 128
    dim3 gD(DD / 64, BSZ / 128);    // 8  x 128

    mm_kernel<DD, 3, 64, true ><<<gL, blk, SM_L>>>(xh,  w0h, b_ih0, b_hh0, nullptr, h0h);
    mm_kernel<HD, 3, 64, true ><<<gL, blk, SM_L>>>(h0h, w1h, b_ih1, b_hh1, nullptr, h1h);
    mm_kernel<HD, 1, 64, false><<<gD, blk, SM_D>>>(h1h, wdh, b_dec, nullptr, out, nullptr);
}

// round 15
// speedup vs baseline: 1.3041x; 1.3041x over previous
#include <cuda_runtime.h>
#include <cuda_fp16.h>
#include <cstdint>

static constexpr int BSZ = 16384;
static constexpr int HD  = 1024;
static constexpr int DD  = 512;

// ---------------- device scratch (allocation-free contract) ----------------
__device__ __align__(256) __half g_x_h [(size_t)BSZ * DD];
__device__ __align__(256) __half g_h0_h[(size_t)BSZ * HD];
__device__ __align__(256) __half g_h1_h[(size_t)BSZ * HD];
__device__ __align__(256) __half g_w0_h[(size_t)4 * HD * DD];
__device__ __align__(256) __half g_w1_h[(size_t)4 * HD * HD];
__device__ __align__(256) __half g_wd_h[(size_t)DD * HD];

// ---------------- helpers ----------------
__device__ __forceinline__ uint32_t smem_u32(const void* p) {
    uint32_t a;
    asm("{ .reg .u64 t; cvta.to.shared.u64 t, %1; cvt.u32.u64 %0, t; }" : "=r"(a) : "l"(p));
    return a;
}
__device__ __forceinline__ void cpa16(uint32_t dst, const void* src) {
    asm volatile("cp.async.cg.shared.global [%0], [%1], 16;\n" :: "r"(dst), "l"(src));
}
__device__ __forceinline__ void ldsm4(uint32_t* r, uint32_t a) {
    asm volatile("ldmatrix.sync.aligned.m8n8.x4.shared.b16 {%0,%1,%2,%3}, [%4];"
        : "=r"(r[0]), "=r"(r[1]), "=r"(r[2]), "=r"(r[3]) : "r"(a));
}
// f32-accumulate mma — proven at the 277 TF/s legacy ceiling (99% achieved in R11).
__device__ __forceinline__ void mma16816(float* d, const uint32_t* a, const uint32_t* b) {
    asm volatile("mma.sync.aligned.m16n8k16.row.col.f32.f16.f16.f32 "
        "{%0,%1,%2,%3}, {%4,%5,%6,%7}, {%8,%9}, {%0,%1,%2,%3};"
        : "+f"(d[0]), "+f"(d[1]), "+f"(d[2]), "+f"(d[3])
        : "r"(a[0]), "r"(a[1]), "r"(a[2]), "r"(a[3]), "r"(b[0]), "r"(b[1]));
}
__device__ __forceinline__ float sigm(float x) { return 1.0f / (1.0f + __expf(-x)); }
__device__ __forceinline__ float tanh_e(float x) {
    float ax = fabsf(x);
    float e  = __expf(2.0f * ax);
    float t  = 1.0f - 2.0f / (1.0f + e);
    return copysignf(t, x);
}

// ---------------- fused fp32 -> fp16 conversion (single launch, 4 regions) ----
// Region boundaries in float4 units; each thread locates its region and converts.
__global__ void cvt_all_kernel(const float4* __restrict__ sx,  __half2* __restrict__ dx,
                               const float4* __restrict__ sw0, __half2* __restrict__ dw0,
                               const float4* __restrict__ sw1, __half2* __restrict__ dw1,
                               const float4* __restrict__ swd, __half2* __restrict__ dwd,
                               int n4x, int n4w0, int n4w1, int n4wd) {
    int i = blockIdx.x * blockDim.x + threadIdx.x;
    const float4* src;
    __half2* dst;
    int j = i;
    if (j < n4x)                    { src = sx;  dst = dx;  }
    else if ((j -= n4x)  < n4w0)    { src = sw0; dst = dw0; }
    else if ((j -= n4w0) < n4w1)    { src = sw1; dst = dw1; }
    else if ((j -= n4w1) < n4wd)    { src = swd; dst = dwd; }
    else return;
    float4 v = src[j];
    dst[2 * j + 0] = __floats2half2_rn(v.x, v.y);
    dst[2 * j + 1] = __floats2half2_rn(v.z, v.w);
}

// ---------------- fused mma.sync GEMM (fp16 f32-acc, 2-stage, occ=2 CTAs/SM) ----
// NG==3: gates i/g/o of A @ W^T (f-gate dead), LSTM-cell epilogue -> h (fp16).
// NG==1: decoder A @ W^T + b -> fp32.
template<int K, int NG, int NT>
__global__ void __launch_bounds__(256, 2)
mm_kernel(const __half* __restrict__ Ah, const __half* __restrict__ Wh,
          const float* __restrict__ b0, const float* __restrict__ b1,
          float* __restrict__ outF, __half* __restrict__ outH)
{
    constexpr int PITCH  = 144;              // 64 fp16 + 8 pad -> ldmatrix conflict-free
    constexpr int ASZ    = 128 * PITCH;
    constexpr int WSZ    = NT * PITCH;
    constexpr int STAGE  = ASZ + NG * WSZ;
    constexpr int NSTG   = 2;
    constexpr int NCHUNK = K / 64;
    constexpr int NFRAG  = NT / 16;          // n8 frags per warp per gate (warp spans NT/2)
    constexpr int NPAIR  = NFRAG / 2;

    extern __shared__ char smem[];
    const uint32_t sb = smem_u32(smem);
    float* bs = (float*)(smem + NSTG * STAGE);

    const int tid = threadIdx.x, wid = tid >> 5, lane = tid & 31;
    const int wm = wid & 3, wn = wid >> 2;
    const int row0 = blockIdx.y * 128, col0 = blockIdx.x * NT;

    // bias sums -> smem (consumed only in epilogue; barriers in between)
    for (int i = tid; i < NG * NT; i += 256) {
        int g = i / NT, n = i - g * NT;
        int go = (NG == 3) ? ((g == 0) ? 0 : (g == 1 ? 2 * HD : 3 * HD)) : 0;
        float bv = b0[go + col0 + n];
        if (NG == 3) bv += b1[go + col0 + n];
        bs[i] = bv;
    }

    const int lr = tid >> 3;     // 0..31 row within 32-row slab
    const int lc = tid & 7;      // 16B chunk within 64-fp16 row

    auto load_chunk = [&](int s, int ck) {
        const int k0 = ck * 64;
        const uint32_t st = sb + s * STAGE;
        #pragma unroll
        for (int it = 0; it < 4; it++) {
            int r = lr + it * 32;
            cpa16(st + r * PITCH + lc * 16, Ah + (size_t)(row0 + r) * K + k0 + lc * 8);
        }
        #pragma unroll
        for (int g = 0; g < NG; g++) {
            const int go = (NG == 3) ? ((g == 0) ? 0 : (g == 1 ? 2 * HD : 3 * HD)) : 0;
            uint32_t wb = st + ASZ + g * WSZ;
            #pragma unroll
            for (int it = 0; it < NT / 32; it++) {
                int r = lr + it * 32;
                cpa16(wb + r * PITCH + lc * 16,
                      Wh + (size_t)(go + col0 + r) * K + k0 + lc * 8);
            }
        }
        asm volatile("cp.async.commit_group;" ::: "memory");
    };

    // ldmatrix per-lane base offsets.
    uint32_t aOff[2];
    #pragma unroll
    for (int f = 0; f < 2; f++)
        aOff[f] = (uint32_t)((wm * 32 + f * 16 + (lane & 15)) * PITCH + (lane >> 4) * 16);
    // W stored [n][k] -> non-trans ldmatrix gives exactly the B fragment (n = l/4, k = 2*(l%4)).
    uint32_t bOff[NPAIR];
    #pragma unroll
    for (int p = 0; p < NPAIR; p++)
        bOff[p] = (uint32_t)((wn * (NT / 2) + p * 16 + (lane & 7) + ((lane >> 4) & 1) * 8) * PITCH
                             + ((lane >> 3) & 1) * 16);

    float acc[NG][2][NFRAG][4];
    #pragma unroll
    for (int g = 0; g < NG; g++)
        #pragma unroll
        for (int f = 0; f < 2; f++)
            #pragma unroll
            for (int j = 0; j < NFRAG; j++)
                #pragma unroll
                for (int q = 0; q < 4; q++) acc[g][f][j][q] = 0.0f;

    load_chunk(0, 0);

    // 2-stage mainloop, ONE barrier per chunk.
    // iter k: wait(chunk k) -> barrier -> issue load k+1 -> compute k.
    for (int k = 0; k < NCHUNK; k++) {
        const int s = k % NSTG;
        asm volatile("cp.async.wait_group 0;" ::: "memory");
        __syncthreads();
        if (k + 1 < NCHUNK) load_chunk((k + 1) % NSTG, k + 1);

        const uint32_t st = sb + s * STAGE;
        #pragma unroll
        for (int ks = 0; ks < 4; ks++) {
            uint32_t aF[2][4];
            ldsm4(aF[0], st + aOff[0] + ks * 32);
            ldsm4(aF[1], st + aOff[1] + ks * 32);
            #pragma unroll
            for (int g = 0; g < NG; g++) {
                const uint32_t wb = st + ASZ + g * WSZ;
                uint32_t bh[NPAIR][4];
                #pragma unroll
                for (int p = 0; p < NPAIR; p++)
                    ldsm4(bh[p], wb + bOff[p] + ks * 32);
                #pragma unroll
                for (int f = 0; f < 2; f++)
                    #pragma unroll
                    for (int j = 0; j < NFRAG; j++)
                        mma16816(acc[g][f][j], aF[f], &bh[j >> 1][(j & 1) * 2]);
            }
        }
    }

    // ---------------- epilogue ----------------
    const int mBase = row0 + wm * 32 + (lane >> 2);
    const int nLoc0 = wn * (NT / 2) + (lane & 3) * 2;      // col offset within tile

    if constexpr (NG == 3) {
        #pragma unroll
        for (int f = 0; f < 2; f++)
            #pragma unroll
            for (int j = 0; j < NFRAG; j++)
                #pragma unroll
                for (int hh = 0; hh < 2; hh++) {
                    int m = mBase + f * 16 + hh * 8;
                    int nl = nLoc0 + j * 8;
                    float h2[2];
                    #pragma unroll
                    for (int u = 0; u < 2; u++) {
                        float iv = sigm(acc[0][f][j][hh * 2 + u] + bs[0 * NT + nl + u]);
                        float gv = tanh_e(acc[1][f][j][hh * 2 + u] + bs[1 * NT + nl + u]);
                        float ov = sigm(acc[2][f][j][hh * 2 + u] + bs[2 * NT + nl + u]);
                        h2[u] = ov * tanh_e(iv * gv);
                    }
                    *(__half2*)(outH + (size_t)m * HD + col0 + nl) = __floats2half2_rn(h2[0], h2[1]);
                }
    } else {
        #pragma unroll
        for (int f = 0; f < 2; f++)
            #pragma unroll
            for (int j = 0; j < NFRAG; j++)
                #pragma unroll
                for (int hh = 0; hh < 2; hh++) {
                    int m = mBase + f * 16 + hh * 8;
                    int nl = nLoc0 + j * 8;
                    float2 v;
                    v.x = acc[0][f][j][hh * 2 + 0] + bs[nl + 0];
                    v.y = acc[0][f][j][hh * 2 + 1] + bs[nl + 1];
                    *(float2*)(outF + (size_t)m * DD + col0 + nl) = v;
                }
    }
}

// ---------------- launch ----------------
extern "C" void kernel_launch(void* const* d_in, const int* in_sizes, int n_in,
                              void* d_out, int out_size) {
    const float* x     = (const float*)d_in[0];
    const float* W_ih0 = (const float*)d_in[1];
    const float* b_ih0 = (const float*)d_in[3];
    const float* b_hh0 = (const float*)d_in[4];
    const float* W_ih1 = (const float*)d_in[5];
    const float* b_ih1 = (const float*)d_in[7];
    const float* b_hh1 = (const float*)d_in[8];
    const float* W_dec = (const float*)d_in[9];
    const float* b_dec = (const float*)d_in[10];
    float* out = (float*)d_out;

    __half *xh, *h0h, *h1h, *w0h, *w1h, *wdh;
    cudaGetSymbolAddress((void**)&xh,  g_x_h);
    cudaGetSymbolAddress((void**)&h0h, g_h0_h);
    cudaGetSymbolAddress((void**)&h1h, g_h1_h);
    cudaGetSymbolAddress((void**)&w0h, g_w0_h);
    cudaGetSymbolAddress((void**)&w1h, g_w1_h);
    cudaGetSymbolAddress((void**)&wdh, g_wd_h);

    // shared-memory sizes (2 stages; LSTM 2 CTAs/SM: 2 x 92928 = 186 KB < 228 KB)
    constexpr int PITCH = 144;
    constexpr int STAGE_L = 128 * PITCH + 3 * 64 * PITCH;     // 46080
    constexpr int STAGE_D = 128 * PITCH + 1 * 32 * PITCH;     // 23040
    constexpr int SM_L = 2 * STAGE_L + 3 * 64 * 4;            // 92928
    constexpr int SM_D = 2 * STAGE_D + 1 * 32 * 4;            // 46208
    cudaFuncSetAttribute(mm_kernel<DD, 3, 64>, cudaFuncAttributeMaxDynamicSharedMemorySize, SM_L);
    cudaFuncSetAttribute(mm_kernel<HD, 3, 64>, cudaFuncAttributeMaxDynamicSharedMemorySize, SM_L);
    cudaFuncSetAttribute(mm_kernel<HD, 1, 32>, cudaFuncAttributeMaxDynamicSharedMemorySize, SM_D);

    // single fused conversion launch (x, W0, W1, Wdec)
    constexpr int n4x  = (int)((size_t)BSZ * DD / 4);
    constexpr int n4w0 = (int)((size_t)4 * HD * DD / 4);
    constexpr int n4w1 = (int)((size_t)4 * HD * HD / 4);
    constexpr int n4wd = (int)((size_t)DD * HD / 4);
    constexpr int n4all = n4x + n4w0 + n4w1 + n4wd;
    cvt_all_kernel<<<(n4all + 255) / 256, 256>>>(
        (const float4*)x,     (__half2*)xh,
        (const float4*)W_ih0, (__half2*)w0h,
        (const float4*)W_ih1, (__half2*)w1h,
        (const float4*)W_dec, (__half2*)wdh,
        n4x, n4w0, n4w1, n4wd);

    dim3 blk(256);
    dim3 gL(HD / 64, BSZ / 128);    // 16 x 128 = 2048 CTAs
    dim3 gD(DD / 32, BSZ / 128);    // 16 x 128 = 2048 CTAs (tail-free decoder)

    mm_kernel<DD, 3, 64><<<gL, blk, SM_L>>>(xh,  w0h, b_ih0, b_hh0, nullptr, h0h);
    mm_kernel<HD, 3, 64><<<gL, blk, SM_L>>>(h0h, w1h, b_ih1, b_hh1, nullptr, h1h);
    mm_kernel<HD, 1, 32><<<gD, blk, SM_D>>>(h1h, wdh, b_dec, nullptr, out, nullptr);
}

// round 16
// speedup vs baseline: 1.3371x; 1.0253x over previous
#include <cuda_runtime.h>
#include <cuda_fp16.h>
#include <cstdint>

static constexpr int BSZ = 16384;
static constexpr int HD  = 1024;
static constexpr int DD  = 512;

// ---------------- device scratch (allocation-free contract) ----------------
__device__ __align__(256) __half g_x_h [(size_t)BSZ * DD];
__device__ __align__(256) __half g_h0_h[(size_t)BSZ * HD];
__device__ __align__(256) __half g_h1_h[(size_t)BSZ * HD];
__device__ __align__(256) __half g_w0_h[(size_t)4 * HD * DD];
__device__ __align__(256) __half g_w1_h[(size_t)4 * HD * HD];
__device__ __align__(256) __half g_wd_h[(size_t)DD * HD];

// ---------------- helpers ----------------
__device__ __forceinline__ uint32_t smem_u32(const void* p) {
    uint32_t a;
    asm("{ .reg .u64 t; cvta.to.shared.u64 t, %1; cvt.u32.u64 %0, t; }" : "=r"(a) : "l"(p));
    return a;
}
__device__ __forceinline__ void cpa16(uint32_t dst, const void* src) {
    asm volatile("cp.async.cg.shared.global [%0], [%1], 16;\n" :: "r"(dst), "l"(src));
}
__device__ __forceinline__ void ldsm4(uint32_t* r, uint32_t a) {
    asm volatile("ldmatrix.sync.aligned.m8n8.x4.shared.b16 {%0,%1,%2,%3}, [%4];"
        : "=r"(r[0]), "=r"(r[1]), "=r"(r[2]), "=r"(r[3]) : "r"(a));
}
// f32-accumulate mma — proven at the 277 TF/s legacy ceiling (99% achieved in R11).
__device__ __forceinline__ void mma16816(float* d, const uint32_t* a, const uint32_t* b) {
    asm volatile("mma.sync.aligned.m16n8k16.row.col.f32.f16.f16.f32 "
        "{%0,%1,%2,%3}, {%4,%5,%6,%7}, {%8,%9}, {%0,%1,%2,%3};"
        : "+f"(d[0]), "+f"(d[1]), "+f"(d[2]), "+f"(d[3])
        : "r"(a[0]), "r"(a[1]), "r"(a[2]), "r"(a[3]), "r"(b[0]), "r"(b[1]));
}
__device__ __forceinline__ float sigm(float x) { return 1.0f / (1.0f + __expf(-x)); }
__device__ __forceinline__ float tanh_e(float x) {
    float ax = fabsf(x);
    float e  = __expf(2.0f * ax);
    float t  = 1.0f - 2.0f / (1.0f + e);
    return copysignf(t, x);
}

// ---------------- fused fp32 -> fp16 conversion (single launch, 4 regions) ----
__global__ void cvt_all_kernel(const float4* __restrict__ sx,  __half2* __restrict__ dx,
                               const float4* __restrict__ sw0, __half2* __restrict__ dw0,
                               const float4* __restrict__ sw1, __half2* __restrict__ dw1,
                               const float4* __restrict__ swd, __half2* __restrict__ dwd,
                               int n4x, int n4w0, int n4w1, int n4wd) {
    int i = blockIdx.x * blockDim.x + threadIdx.x;
    const float4* src;
    __half2* dst;
    int j = i;
    if (j < n4x)                    { src = sx;  dst = dx;  }
    else if ((j -= n4x)  < n4w0)    { src = sw0; dst = dw0; }
    else if ((j -= n4w0) < n4w1)    { src = sw1; dst = dw1; }
    else if ((j -= n4w1) < n4wd)    { src = swd; dst = dwd; }
    else return;
    float4 v = src[j];
    dst[2 * j + 0] = __floats2half2_rn(v.x, v.y);
    dst[2 * j + 1] = __floats2half2_rn(v.z, v.w);
}

// ---------------- fused mma.sync GEMM (fp16 f32-acc, 2-stage, occ=2 CTAs/SM) ----
// NG==3: gates i/g/o of A @ W^T (f-gate dead), LSTM-cell epilogue -> h (fp16).
// NG==1: decoder A @ W^T + b -> fp32.
template<int K, int NG, int NT>
__global__ void __launch_bounds__(256, 2)
mm_kernel(const __half* __restrict__ Ah, const __half* __restrict__ Wh,
          const float* __restrict__ b0, const float* __restrict__ b1,
          float* __restrict__ outF, __half* __restrict__ outH)
{
    constexpr int PITCH  = 144;              // 64 fp16 + 8 pad -> ldmatrix conflict-free
    constexpr int ASZ    = 128 * PITCH;
    constexpr int WSZ    = NT * PITCH;
    constexpr int STAGE  = ASZ + NG * WSZ;
    constexpr int NSTG   = 2;
    constexpr int NCHUNK = K / 64;
    constexpr int NFRAG  = NT / 16;          // n8 frags per warp per gate (warp spans NT/2)
    constexpr int NPAIR  = NFRAG / 2;

    extern __shared__ char smem[];
    const uint32_t sb = smem_u32(smem);
    float* bs = (float*)(smem + NSTG * STAGE);

    const int tid = threadIdx.x, wid = tid >> 5, lane = tid & 31;
    const int wm = wid & 3, wn = wid >> 2;
    const int row0 = blockIdx.y * 128, col0 = blockIdx.x * NT;

    // bias sums -> smem (consumed only in epilogue; barriers in between)
    for (int i = tid; i < NG * NT; i += 256) {
        int g = i / NT, n = i - g * NT;
        int go = (NG == 3) ? ((g == 0) ? 0 : (g == 1 ? 2 * HD : 3 * HD)) : 0;
        float bv = b0[go + col0 + n];
        if (NG == 3) bv += b1[go + col0 + n];
        bs[i] = bv;
    }

    const int lr = tid >> 3;     // 0..31 row within 32-row slab
    const int lc = tid & 7;      // 16B chunk within 64-fp16 row

    auto load_chunk = [&](int s, int ck) {
        const int k0 = ck * 64;
        const uint32_t st = sb + s * STAGE;
        #pragma unroll
        for (int it = 0; it < 4; it++) {
            int r = lr + it * 32;
            cpa16(st + r * PITCH + lc * 16, Ah + (size_t)(row0 + r) * K + k0 + lc * 8);
        }
        #pragma unroll
        for (int g = 0; g < NG; g++) {
            const int go = (NG == 3) ? ((g == 0) ? 0 : (g == 1 ? 2 * HD : 3 * HD)) : 0;
            uint32_t wb = st + ASZ + g * WSZ;
            #pragma unroll
            for (int it = 0; it < NT / 32; it++) {
                int r = lr + it * 32;
                cpa16(wb + r * PITCH + lc * 16,
                      Wh + (size_t)(go + col0 + r) * K + k0 + lc * 8);
            }
        }
        asm volatile("cp.async.commit_group;" ::: "memory");
    };

    // ldmatrix per-lane base offsets.
    uint32_t aOff[2];
    #pragma unroll
    for (int f = 0; f < 2; f++)
        aOff[f] = (uint32_t)((wm * 32 + f * 16 + (lane & 15)) * PITCH + (lane >> 4) * 16);
    // W stored [n][k] -> non-trans ldmatrix gives exactly the B fragment (n = l/4, k = 2*(l%4)).
    uint32_t bOff[NPAIR];
    #pragma unroll
    for (int p = 0; p < NPAIR; p++)
        bOff[p] = (uint32_t)((wn * (NT / 2) + p * 16 + (lane & 7) + ((lane >> 4) & 1) * 8) * PITCH
                             + ((lane >> 3) & 1) * 16);

    float acc[NG][2][NFRAG][4];
    #pragma unroll
    for (int g = 0; g < NG; g++)
        #pragma unroll
        for (int f = 0; f < 2; f++)
            #pragma unroll
            for (int j = 0; j < NFRAG; j++)
                #pragma unroll
                for (int q = 0; q < 4; q++) acc[g][f][j][q] = 0.0f;

    load_chunk(0, 0);

    // 2-stage mainloop, ONE barrier per chunk.
    // iter k: wait(chunk k) -> barrier -> issue load k+1 -> compute k.
    for (int k = 0; k < NCHUNK; k++) {
        const int s = k % NSTG;
        asm volatile("cp.async.wait_group 0;" ::: "memory");
        __syncthreads();
        if (k + 1 < NCHUNK) load_chunk((k + 1) % NSTG, k + 1);

        const uint32_t st = sb + s * STAGE;
        #pragma unroll
        for (int ks = 0; ks < 4; ks++) {
            uint32_t aF[2][4];
            ldsm4(aF[0], st + aOff[0] + ks * 32);
            ldsm4(aF[1], st + aOff[1] + ks * 32);
            #pragma unroll
            for (int g = 0; g < NG; g++) {
                const uint32_t wb = st + ASZ + g * WSZ;
                uint32_t bh[NPAIR][4];
                #pragma unroll
                for (int p = 0; p < NPAIR; p++)
                    ldsm4(bh[p], wb + bOff[p] + ks * 32);
                #pragma unroll
                for (int f = 0; f < 2; f++)
                    #pragma unroll
                    for (int j = 0; j < NFRAG; j++)
                        mma16816(acc[g][f][j], aF[f], &bh[j >> 1][(j & 1) * 2]);
            }
        }
    }

    // ---------------- epilogue ----------------
    const int mBase = row0 + wm * 32 + (lane >> 2);
    const int nLoc0 = wn * (NT / 2) + (lane & 3) * 2;      // col offset within tile

    if constexpr (NG == 3) {
        #pragma unroll
        for (int f = 0; f < 2; f++)
            #pragma unroll
            for (int j = 0; j < NFRAG; j++)
                #pragma unroll
                for (int hh = 0; hh < 2; hh++) {
                    int m = mBase + f * 16 + hh * 8;
                    int nl = nLoc0 + j * 8;
                    float h2[2];
                    #pragma unroll
                    for (int u = 0; u < 2; u++) {
                        float iv = sigm(acc[0][f][j][hh * 2 + u] + bs[0 * NT + nl + u]);
                        float gv = tanh_e(acc[1][f][j][hh * 2 + u] + bs[1 * NT + nl + u]);
                        float ov = sigm(acc[2][f][j][hh * 2 + u] + bs[2 * NT + nl + u]);
                        h2[u] = ov * tanh_e(iv * gv);
                    }
                    *(__half2*)(outH + (size_t)m * HD + col0 + nl) = __floats2half2_rn(h2[0], h2[1]);
                }
    } else {
        #pragma unroll
        for (int f = 0; f < 2; f++)
            #pragma unroll
            for (int j = 0; j < NFRAG; j++)
                #pragma unroll
                for (int hh = 0; hh < 2; hh++) {
                    int m = mBase + f * 16 + hh * 8;
                    int nl = nLoc0 + j * 8;
                    float2 v;
                    v.x = acc[0][f][j][hh * 2 + 0] + bs[nl + 0];
                    v.y = acc[0][f][j][hh * 2 + 1] + bs[nl + 1];
                    *(float2*)(outF + (size_t)m * DD + col0 + nl) = v;
                }
    }
}

// ---------------- launch ----------------
extern "C" void kernel_launch(void* const* d_in, const int* in_sizes, int n_in,
                              void* d_out, int out_size) {
    const float* x     = (const float*)d_in[0];
    const float* W_ih0 = (const float*)d_in[1];
    const float* b_ih0 = (const float*)d_in[3];
    const float* b_hh0 = (const float*)d_in[4];
    const float* W_ih1 = (const float*)d_in[5];
    const float* b_ih1 = (const float*)d_in[7];
    const float* b_hh1 = (const float*)d_in[8];
    const float* W_dec = (const float*)d_in[9];
    const float* b_dec = (const float*)d_in[10];
    float* out = (float*)d_out;

    __half *xh, *h0h, *h1h, *w0h, *w1h, *wdh;
    cudaGetSymbolAddress((void**)&xh,  g_x_h);
    cudaGetSymbolAddress((void**)&h0h, g_h0_h);
    cudaGetSymbolAddress((void**)&h1h, g_h1_h);
    cudaGetSymbolAddress((void**)&w0h, g_w0_h);
    cudaGetSymbolAddress((void**)&w1h, g_w1_h);
    cudaGetSymbolAddress((void**)&wdh, g_wd_h);

    // shared-memory sizes (2 stages; 2 CTAs/SM: 2 x 92928 = 186 KB < 228 KB)
    constexpr int PITCH = 144;
    constexpr int STAGE_L = 128 * PITCH + 3 * 64 * PITCH;     // 46080
    constexpr int STAGE_D = 128 * PITCH + 1 * 64 * PITCH;     // 27648
    constexpr int SM_L = 2 * STAGE_L + 3 * 64 * 4;            // 92928
    constexpr int SM_D = 2 * STAGE_D + 1 * 64 * 4;            // 55552
    cudaFuncSetAttribute(mm_kernel<DD, 3, 64>, cudaFuncAttributeMaxDynamicSharedMemorySize, SM_L);
    cudaFuncSetAttribute(mm_kernel<HD, 3, 64>, cudaFuncAttributeMaxDynamicSharedMemorySize, SM_L);
    cudaFuncSetAttribute(mm_kernel<HD, 1, 64>, cudaFuncAttributeMaxDynamicSharedMemorySize, SM_D);

    // single fused conversion launch (x, W0, W1, Wdec)
    constexpr int n4x  = (int)((size_t)BSZ * DD / 4);
    constexpr int n4w0 = (int)((size_t)4 * HD * DD / 4);
    constexpr int n4w1 = (int)((size_t)4 * HD * HD / 4);
    constexpr int n4wd = (int)((size_t)DD * HD / 4);
    constexpr int n4all = n4x + n4w0 + n4w1 + n4wd;
    cvt_all_kernel<<<(n4all + 255) / 256, 256>>>(
        (const float4*)x,     (__half2*)xh,
        (const float4*)W_ih0, (__half2*)w0h,
        (const float4*)W_ih1, (__half2*)w1h,
        (const float4*)W_dec, (__half2*)wdh,
        n4x, n4w0, n4w1, n4wd);

    dim3 blk(256);
    dim3 gL(HD / 64, BSZ / 128);    // 16 x 128 = 2048 CTAs
    dim3 gD(DD / 64, BSZ / 128);    // 8  x 128 = 1024 CTAs (proven R11 decoder)

    mm_kernel<DD, 3, 64><<<gL, blk, SM_L>>>(xh,  w0h, b_ih0, b_hh0, nullptr, h0h);
    mm_kernel<HD, 3, 64><<<gL, blk, SM_L>>>(h0h, w1h, b_ih1, b_hh1, nullptr, h1h);
    mm_kernel<HD, 1, 64><<<gD, blk, SM_D>>>(h1h, wdh, b_dec, nullptr, out, nullptr);
}